// round 3
// baseline (speedup 1.0000x reference)
#include <cuda_runtime.h>

#define NNODE 131072
#define NEDGE 2097152
#define BATCH 64
#define NPG   2048
#define KDIM  20480   // N * CS
#define HID   512
#define EC    4       // edges per gather thread

// ---------------- scratch (device globals; no allocation) ----------------
__device__ __align__(16) float g_deg[NNODE];            // degree -> dinv (in place)
__device__ __align__(16) int   g_cnt[NNODE];            // edge counts per row
__device__ __align__(16) int   g_rowstart[NNODE];       // CSR row starts (exclusive scan)
__device__ __align__(16) int   g_cursor[NNODE];         // fill cursors
__device__             int     g_bsum[512];             // scan block sums
__device__ __align__(16) int   g_ecol[NEDGE];           // CSR: col per slot
__device__ __align__(16) float g_ewn[NEDGE];            // CSR: normalized weight per slot
__device__ __align__(16) int   g_erow[NEDGE];           // CSR: row per slot
__device__ __align__(16) float g_T0[NNODE * 20];        // [node][ch] 0..9 real, 10..19 imag
__device__ __align__(16) float g_B1[NNODE * 20];        // S1 -> T1 (in place)
__device__ __align__(16) float g_B2[NNODE * 20];        // S2
__device__ __align__(16) float g_zr[BATCH * KDIM];
__device__ __align__(16) float g_zi[BATCH * KDIM];
__device__ __align__(16) float g_accU[2 * BATCH * HID];
__device__ __align__(16) float g_cat[BATCH * 2 * HID];

// ---------------- helpers ----------------
__device__ __forceinline__ void red4(float* p, float a, float b, float c, float d) {
    // no memory clobber: target array never read within the issuing kernel
    asm volatile("red.global.add.v4.f32 [%0], {%1,%2,%3,%4};"
                 :: "l"(p), "f"(a), "f"(b), "f"(c), "f"(d));
}
__device__ __forceinline__ void fma2(unsigned long long& d,
                                     unsigned long long a, unsigned long long b) {
    asm("fma.rn.f32x2 %0, %1, %2, %3;" : "=l"(d) : "l"(a), "l"(b), "l"(d));
}

// ---------------- stage 0: init, degree+count ----------------
__global__ void k_init() {
    int i = blockIdx.x * 256 + threadIdx.x;
    g_deg[i] = 0.f;
    g_cnt[i] = 0;
}
__global__ void k_degcnt(const int* __restrict__ row, const float* __restrict__ ew) {
    int e = blockIdx.x * 256 + threadIdx.x;
    int r = row[e];
    atomicAdd(&g_deg[r], ew[e]);
    atomicAdd(&g_cnt[r], 1);
}

// ---------------- CSR scan (3 kernels) ----------------
__global__ __launch_bounds__(256) void k_scan1() {
    __shared__ int s[256];
    int t = threadIdx.x;
    int i = blockIdx.x * 256 + t;
    int v = g_cnt[i];
    s[t] = v;
    __syncthreads();
#pragma unroll
    for (int off = 1; off < 256; off <<= 1) {
        int a = (t >= off) ? s[t - off] : 0;
        __syncthreads();
        s[t] += a;
        __syncthreads();
    }
    g_rowstart[i] = s[t] - v;   // exclusive within block
    if (t == 255) g_bsum[blockIdx.x] = s[255];
}
__global__ __launch_bounds__(512) void k_scan2() {
    __shared__ int s[512];
    int t = threadIdx.x;
    int v = g_bsum[t];
    s[t] = v;
    __syncthreads();
#pragma unroll
    for (int off = 1; off < 512; off <<= 1) {
        int a = (t >= off) ? s[t - off] : 0;
        __syncthreads();
        s[t] += a;
        __syncthreads();
    }
    g_bsum[t] = s[t] - v;       // exclusive block offsets
}
__global__ void k_scan3() {  // finalize rowstart, cursors; deg -> dinv
    int i = blockIdx.x * 256 + threadIdx.x;
    int rs = g_rowstart[i] + g_bsum[i >> 8];
    g_rowstart[i] = rs;
    g_cursor[i] = rs;
    float d = g_deg[i];
    g_deg[i] = (d > 0.f) ? rsqrtf(d + 1e-6f) : 0.f;
}

// ---------------- CSR fill (wn fused) ----------------
__global__ void k_fill(const int* __restrict__ row, const int* __restrict__ col,
                       const float* __restrict__ ew) {
    int e = blockIdx.x * 256 + threadIdx.x;
    int r = row[e], c = col[e];
    float w = ew[e] * g_deg[r] * g_deg[c];
    int pos = atomicAdd(&g_cursor[r], 1);
    g_ecol[pos] = c;
    g_ewn[pos] = w;
    g_erow[pos] = r;
}

// ---------------- stage 1: conv1 (complex 1x1) + relu -> T0; zero B1 ----------------
__global__ __launch_bounds__(256) void k_conv(const float* __restrict__ xr,
                                              const float* __restrict__ xi,
                                              const float* __restrict__ wr,
                                              const float* __restrict__ wi,
                                              const float* __restrict__ br,
                                              const float* __restrict__ bi) {
    __shared__ float swr[100], swi[100], sbr[10], sbi[10];
    int t = threadIdx.x;
    if (t < 100) { swr[t] = wr[t]; swi[t] = wi[t]; }
    if (t < 10)  { sbr[t] = br[t]; sbi[t] = bi[t]; }
    __syncthreads();
    int n = blockIdx.x * 256 + t;
    float a[10], b_[10];
#pragma unroll
    for (int k = 0; k < 10; k++) { a[k] = xr[n * 10 + k]; b_[k] = xi[n * 10 + k]; }
    float* o = g_T0 + n * 20;
#pragma unroll
    for (int c = 0; c < 10; c++) {
        float yr = sbr[c], yi = sbi[c];
#pragma unroll
        for (int k = 0; k < 10; k++) {
            yr += a[k] * swr[c * 10 + k] - b_[k] * swi[c * 10 + k];
            yi += a[k] * swi[c * 10 + k] + b_[k] * swr[c * 10 + k];
        }
        o[c]      = fmaxf(yr, 0.f);
        o[10 + c] = fmaxf(yi, 0.f);
    }
    float4 z4 = make_float4(0.f, 0.f, 0.f, 0.f);
    float4* b1 = (float4*)(g_B1 + n * 20);
#pragma unroll
    for (int j = 0; j < 5; j++) b1[j] = z4;
}

// ---------------- CSR gather: S += wn * X[col], balanced edge chunks ----------------
// phase 0: X=T0 -> S=B1.  phase 1: X=B1 -> S=B2.
__global__ __launch_bounds__(256) void k_gather(int phase) {
    const float* __restrict__ X = (phase == 0) ? g_T0 : g_B1;
    float* S = (phase == 0) ? g_B1 : g_B2;
    int t = blockIdx.x * 256 + threadIdx.x;
    int base = t * EC;

    int4 ci = *(const int4*)(g_ecol + base);
    int4 ri = *(const int4*)(g_erow + base);
    float4 wi4 = *(const float4*)(g_ewn + base);
    int c[EC] = {ci.x, ci.y, ci.z, ci.w};
    int r[EC] = {ri.x, ri.y, ri.z, ri.w};
    float w[EC] = {wi4.x, wi4.y, wi4.z, wi4.w};

    // prefetch all gathered node rows (MLP = 20 loads)
    float4 v[EC][5];
#pragma unroll
    for (int j = 0; j < EC; j++) {
        const float4* src = (const float4*)(X + c[j] * 20);
#pragma unroll
        for (int k = 0; k < 5; k++) v[j][k] = src[k];
    }

    float acc[20];
    int cur = r[0];
#pragma unroll
    for (int k = 0; k < 5; k++) {
        acc[4 * k + 0] = w[0] * v[0][k].x;
        acc[4 * k + 1] = w[0] * v[0][k].y;
        acc[4 * k + 2] = w[0] * v[0][k].z;
        acc[4 * k + 3] = w[0] * v[0][k].w;
    }
#pragma unroll
    for (int j = 1; j < EC; j++) {
        if (r[j] != cur) {
            float* sp = S + cur * 20;
#pragma unroll
            for (int k = 0; k < 5; k++)
                red4(sp + 4 * k, acc[4 * k], acc[4 * k + 1], acc[4 * k + 2], acc[4 * k + 3]);
            cur = r[j];
#pragma unroll
            for (int k = 0; k < 20; k++) acc[k] = 0.f;
        }
#pragma unroll
        for (int k = 0; k < 5; k++) {
            acc[4 * k + 0] += w[j] * v[j][k].x;
            acc[4 * k + 1] += w[j] * v[j][k].y;
            acc[4 * k + 2] += w[j] * v[j][k].z;
            acc[4 * k + 3] += w[j] * v[j][k].w;
        }
    }
    float* sp = S + cur * 20;
#pragma unroll
    for (int k = 0; k < 5; k++)
        red4(sp + 4 * k, acc[4 * k], acc[4 * k + 1], acc[4 * k + 2], acc[4 * k + 3]);
}

// ---------------- pointwise: T1 = T0 - S1 (into B1); zero B2 ----------------
__global__ void k_t1() {
    int i = blockIdx.x * 256 + threadIdx.x;  // over NN*5 float4
    float4 t0 = ((const float4*)g_T0)[i];
    float4 s  = ((const float4*)g_B1)[i];
    ((float4*)g_B1)[i] = make_float4(t0.x - s.x, t0.y - s.y, t0.z - s.z, t0.w - s.w);
    ((float4*)g_B2)[i] = make_float4(0.f, 0.f, 0.f, 0.f);
}

// ---------------- cheb combine ----------------
__global__ __launch_bounds__(256) void k_cheb(const float* __restrict__ cw,
                                              const float* __restrict__ cb) {
    __shared__ float scw[300], scb[10];
    int t = threadIdx.x;
    for (int i = t; i < 300; i += 256) scw[i] = cw[i];
    if (t < 10) scb[t] = cb[t];
    __syncthreads();
    int n = blockIdx.x * 256 + t;
    float t0[20], t1[20], t2[20];
#pragma unroll
    for (int j = 0; j < 20; j++) {
        t0[j] = g_T0[n * 20 + j];
        t1[j] = g_B1[n * 20 + j];
        t2[j] = 2.f * (t1[j] - g_B2[n * 20 + j]) - t0[j];
    }
    int b = n >> 11;
    int nl = n & (NPG - 1);
    int base = b * KDIM + nl * 10;
#pragma unroll
    for (int o = 0; o < 10; o++) {
        float ar = scb[o], ai = 0.f;
#pragma unroll
        for (int i2 = 0; i2 < 10; i2++) {
            float w0 = scw[i2 * 10 + o], w1 = scw[100 + i2 * 10 + o], w2 = scw[200 + i2 * 10 + o];
            ar += t0[i2] * w0 + t1[i2] * w1 + t2[i2] * w2;
            ai += t0[10 + i2] * w0 + t1[10 + i2] * w1 + t2[10 + i2] * w2;
        }
        g_zr[base + o] = fmaxf(ar, 0.f);
        g_zi[base + o] = fmaxf(ai, 0.f);
    }
}

// ---------------- zero GEMM accumulators ----------------
__global__ void k_zacc() {
    int i = blockIdx.x * 256 + threadIdx.x;
    g_accU[i] = 0.f;
}

// ---------------- fc1 complex GEMM (fp32 f32x2, k-split) ----------------
__global__ __launch_bounds__(256) void k_fc1(const float* __restrict__ Wr,
                                             const float* __restrict__ Wi) {
    __shared__ float2 s_zr[16][65];
    __shared__ float2 s_zi[16][65];
    __shared__ float2 s_wr[16][17];
    __shared__ float2 s_wi[16][17];

    const int t = threadIdx.x;
    const int h0 = blockIdx.x * 32;
    const int kbase0 = blockIdx.y * 1280;
    const int bg = t & 31;
    const int hpg = t >> 5;

    unsigned long long P[2][2][4];
#pragma unroll
    for (int a = 0; a < 2; a++)
#pragma unroll
        for (int b = 0; b < 2; b++)
#pragma unroll
            for (int c = 0; c < 4; c++) P[a][b][c] = 0ULL;

    for (int kc = 0; kc < 1280; kc += 16) {
        const int kb = kbase0 + kc;
#pragma unroll
        for (int p = 0; p < 4; p++) {
            int idx = t + p * 256;
            int kk = idx & 15, b = idx >> 4;
            float vr = g_zr[b * KDIM + kb + kk];
            float vi = g_zi[b * KDIM + kb + kk];
            s_zr[kk][b] = make_float2(vr, vr);
            s_zi[kk][b] = make_float2(vi, vi);
        }
        {
            int kk = t & 15, hp = t >> 4;
            int h = h0 + 2 * hp;
            s_wr[kk][hp] = make_float2(Wr[h * KDIM + kb + kk], Wr[(h + 1) * KDIM + kb + kk]);
            s_wi[kk][hp] = make_float2(Wi[h * KDIM + kb + kk], Wi[(h + 1) * KDIM + kb + kk]);
        }
        __syncthreads();
#pragma unroll
        for (int kk = 0; kk < 16; kk++) {
            unsigned long long zr0 = *(const unsigned long long*)&s_zr[kk][bg];
            unsigned long long zr1 = *(const unsigned long long*)&s_zr[kk][bg + 32];
            unsigned long long zi0 = *(const unsigned long long*)&s_zi[kk][bg];
            unsigned long long zi1 = *(const unsigned long long*)&s_zi[kk][bg + 32];
            unsigned long long wr0 = *(const unsigned long long*)&s_wr[kk][hpg];
            unsigned long long wr1 = *(const unsigned long long*)&s_wr[kk][hpg + 8];
            unsigned long long wi0 = *(const unsigned long long*)&s_wi[kk][hpg];
            unsigned long long wi1 = *(const unsigned long long*)&s_wi[kk][hpg + 8];
            fma2(P[0][0][0], zr0, wr0); fma2(P[0][0][1], zi0, wi0);
            fma2(P[0][0][2], zr0, wi0); fma2(P[0][0][3], zi0, wr0);
            fma2(P[0][1][0], zr1, wr0); fma2(P[0][1][1], zi1, wi0);
            fma2(P[0][1][2], zr1, wi0); fma2(P[0][1][3], zi1, wr0);
            fma2(P[1][0][0], zr0, wr1); fma2(P[1][0][1], zi0, wi1);
            fma2(P[1][0][2], zr0, wi1); fma2(P[1][0][3], zi0, wr1);
            fma2(P[1][1][0], zr1, wr1); fma2(P[1][1][1], zi1, wi1);
            fma2(P[1][1][2], zr1, wi1); fma2(P[1][1][3], zi1, wr1);
        }
        __syncthreads();
    }
#pragma unroll
    for (int hh = 0; hh < 2; hh++) {
        int hp = (hh == 0) ? hpg : (hpg + 8);
        int h = h0 + 2 * hp;
#pragma unroll
        for (int bb = 0; bb < 2; bb++) {
            int b = bg + bb * 32;
            float2 p1 = *(float2*)&P[hh][bb][0];
            float2 p2 = *(float2*)&P[hh][bb][1];
            float2 p3 = *(float2*)&P[hh][bb][2];
            float2 p4 = *(float2*)&P[hh][bb][3];
            atomicAdd(&g_accU[b * HID + h],     p1.x - p2.x);
            atomicAdd(&g_accU[b * HID + h + 1], p1.y - p2.y);
            atomicAdd(&g_accU[BATCH * HID + b * HID + h],     p3.x + p4.x);
            atomicAdd(&g_accU[BATCH * HID + b * HID + h + 1], p3.y + p4.y);
        }
    }
}

// ---------------- bias + relu -> cat ----------------
__global__ void k_relu_cat(const float* __restrict__ fbr, const float* __restrict__ fbi) {
    int i = blockIdx.x * 256 + threadIdx.x;
    int b = i >> 9, h = i & 511;
    g_cat[b * 1024 + h]       = fmaxf(g_accU[i] + fbr[h], 0.f);
    g_cat[b * 1024 + 512 + h] = fmaxf(g_accU[BATCH * HID + i] + fbi[h], 0.f);
}

// ---------------- heads ----------------
__global__ __launch_bounds__(128) void k_head(const float* __restrict__ aw,
                                              const float* __restrict__ ab,
                                              const float* __restrict__ cw,
                                              const float* __restrict__ cb,
                                              float* __restrict__ out) {
    __shared__ float s[1024];
    int b = blockIdx.x;
    for (int i = threadIdx.x; i < 1024; i += 128) s[i] = g_cat[b * 1024 + i];
    __syncthreads();
    int warp = threadIdx.x >> 5, lane = threadIdx.x & 31;
    for (int o = warp; o < 33; o += 4) {
        const float* wrow = (o < 32) ? (aw + o * 1024) : cw;
        float acc = 0.f;
        for (int k = lane; k < 1024; k += 32) acc += s[k] * wrow[k];
#pragma unroll
        for (int off = 16; off; off >>= 1) acc += __shfl_down_sync(0xffffffffu, acc, off);
        if (lane == 0) {
            if (o < 32) out[b * 32 + o] = acc + ab[o];
            else        out[BATCH * 32 + b] = acc + cb[0];
        }
    }
}

// ---------------- launch ----------------
extern "C" void kernel_launch(void* const* d_in, const int* in_sizes, int n_in,
                              void* d_out, int out_size) {
    const float* xr   = (const float*)d_in[0];
    const float* xi   = (const float*)d_in[1];
    const float* ew   = (const float*)d_in[2];
    const float* c1wr = (const float*)d_in[3];
    const float* c1wi = (const float*)d_in[4];
    const float* c1br = (const float*)d_in[5];
    const float* c1bi = (const float*)d_in[6];
    const float* chw  = (const float*)d_in[7];
    const float* chb  = (const float*)d_in[8];
    const float* f1wr = (const float*)d_in[9];
    const float* f1wi = (const float*)d_in[10];
    const float* f1br = (const float*)d_in[11];
    const float* f1bi = (const float*)d_in[12];
    const float* cw   = (const float*)d_in[13];
    const float* cb   = (const float*)d_in[14];
    const float* aw   = (const float*)d_in[15];
    const float* ab   = (const float*)d_in[16];
    const int*   ei   = (const int*)d_in[17];
    const int* row = ei;
    const int* col = ei + NEDGE;
    float* out = (float*)d_out;

    k_init<<<NNODE / 256, 256>>>();
    k_degcnt<<<NEDGE / 256, 256>>>(row, ew);
    k_scan1<<<NNODE / 256, 256>>>();
    k_scan2<<<1, 512>>>();
    k_scan3<<<NNODE / 256, 256>>>();
    k_fill<<<NEDGE / 256, 256>>>(row, col, ew);
    k_conv<<<NNODE / 256, 256>>>(xr, xi, c1wr, c1wi, c1br, c1bi);
    k_gather<<<NEDGE / EC / 256, 256>>>(0);
    k_t1<<<(NNODE * 5) / 256, 256>>>();
    k_gather<<<NEDGE / EC / 256, 256>>>(1);
    k_cheb<<<NNODE / 256, 256>>>(chw, chb);
    k_zacc<<<(2 * BATCH * HID) / 256, 256>>>();
    k_fc1<<<dim3(16, 16), 256>>>(f1wr, f1wi);
    k_relu_cat<<<(BATCH * HID) / 256, 256>>>(f1br, f1bi);
    k_head<<<BATCH, 128>>>(aw, ab, cw, cb, out);
}

// round 5
// speedup vs baseline: 1.3844x; 1.3844x over previous
#include <cuda_runtime.h>
#include <cuda_bf16.h>
#include <cstdint>

#define NNODE 131072
#define NEDGE 2097152
#define BATCH 64
#define NPG   2048
#define KDIM  20480   // N * CS
#define HID   512
#define EC    4       // edges per gather thread

// fc1 mma.sync config: M-tile 128, N=64, k-split 32 x 640, k-chunk 32
#define FC1_KS    32
#define FC1_KBLK  640
#define FC1_KCH   32
#define FC1_NCH   20          // chunks per block (640/32)
#define SA        40          // padded smem row stride (bf16 elements)
// smem matrix offsets (bf16 elements)
#define OFF_WRH   0
#define OFF_WRL   5120
#define OFF_WIH   10240
#define OFF_WIL   15360
#define OFF_ZRH   20480
#define OFF_ZRL   23040
#define OFF_ZIH   25600
#define OFF_ZIL   28160
#define FC1_SMEM_BYTES  (30720 * 2)   // 61440

// ---------------- scratch (device globals; no allocation) ----------------
__device__ __align__(16) float g_deg[NNODE];
__device__ __align__(16) int   g_cnt[NNODE];
__device__ __align__(16) int   g_rowstart[NNODE];
__device__ __align__(16) int   g_cursor[NNODE];
__device__             int     g_bsum[512];
__device__ __align__(16) int   g_ecol[NEDGE];
__device__ __align__(16) float g_ewn[NEDGE];
__device__ __align__(16) int   g_erow[NEDGE];
__device__ __align__(16) float g_T0[NNODE * 20];
__device__ __align__(16) float g_B1[NNODE * 20];
__device__ __align__(16) float g_B2[NNODE * 20];
__device__ __align__(16) float g_zr[BATCH * KDIM];
__device__ __align__(16) float g_zi[BATCH * KDIM];
__device__ __align__(16) float g_accU[2 * BATCH * HID];
__device__ __align__(16) float g_cat[BATCH * 2 * HID];

// ---------------- helpers ----------------
__device__ __forceinline__ void red4(float* p, float a, float b, float c, float d) {
    asm volatile("red.global.add.v4.f32 [%0], {%1,%2,%3,%4};"
                 :: "l"(p), "f"(a), "f"(b), "f"(c), "f"(d));
}
__device__ __forceinline__ void mma16816(float* d, const uint32_t* a, const uint32_t* b) {
    asm volatile("mma.sync.aligned.m16n8k16.row.col.f32.bf16.bf16.f32 "
                 "{%0,%1,%2,%3}, {%4,%5,%6,%7}, {%8,%9}, {%0,%1,%2,%3};"
                 : "+f"(d[0]), "+f"(d[1]), "+f"(d[2]), "+f"(d[3])
                 : "r"(a[0]), "r"(a[1]), "r"(a[2]), "r"(a[3]), "r"(b[0]), "r"(b[1]));
}
__device__ __forceinline__ void cvt_pair(float a, float b, uint32_t& hi, uint32_t& lo) {
    __nv_bfloat16 ha = __float2bfloat16_rn(a);
    __nv_bfloat16 hb = __float2bfloat16_rn(b);
    __nv_bfloat162 hp = __halves2bfloat162(ha, hb);
    __nv_bfloat162 lp = __halves2bfloat162(__float2bfloat16_rn(a - __bfloat162float(ha)),
                                           __float2bfloat16_rn(b - __bfloat162float(hb)));
    hi = *(uint32_t*)&hp;
    lo = *(uint32_t*)&lp;
}

// ---------------- stage 0: init, degree+count ----------------
__global__ void k_init() {
    int i = blockIdx.x * 256 + threadIdx.x;
    g_deg[i] = 0.f;
    g_cnt[i] = 0;
}
__global__ void k_degcnt(const int* __restrict__ row, const float* __restrict__ ew) {
    int e = blockIdx.x * 256 + threadIdx.x;
    int r = row[e];
    atomicAdd(&g_deg[r], ew[e]);
    atomicAdd(&g_cnt[r], 1);
}

// ---------------- CSR scan ----------------
__global__ __launch_bounds__(256) void k_scan1() {
    __shared__ int s[256];
    int t = threadIdx.x;
    int i = blockIdx.x * 256 + t;
    int v = g_cnt[i];
    s[t] = v;
    __syncthreads();
#pragma unroll
    for (int off = 1; off < 256; off <<= 1) {
        int a = (t >= off) ? s[t - off] : 0;
        __syncthreads();
        s[t] += a;
        __syncthreads();
    }
    g_rowstart[i] = s[t] - v;
    if (t == 255) g_bsum[blockIdx.x] = s[255];
}
__global__ __launch_bounds__(512) void k_scan2() {
    __shared__ int s[512];
    int t = threadIdx.x;
    int v = g_bsum[t];
    s[t] = v;
    __syncthreads();
#pragma unroll
    for (int off = 1; off < 512; off <<= 1) {
        int a = (t >= off) ? s[t - off] : 0;
        __syncthreads();
        s[t] += a;
        __syncthreads();
    }
    g_bsum[t] = s[t] - v;
}
__global__ void k_scan3() {
    int i = blockIdx.x * 256 + threadIdx.x;
    int rs = g_rowstart[i] + g_bsum[i >> 8];
    g_rowstart[i] = rs;
    g_cursor[i] = rs;
    float d = g_deg[i];
    g_deg[i] = (d > 0.f) ? rsqrtf(d + 1e-6f) : 0.f;
}

// ---------------- CSR fill ----------------
__global__ void k_fill(const int* __restrict__ row, const int* __restrict__ col,
                       const float* __restrict__ ew) {
    int e = blockIdx.x * 256 + threadIdx.x;
    int r = row[e], c = col[e];
    float w = ew[e] * g_deg[r] * g_deg[c];
    int pos = atomicAdd(&g_cursor[r], 1);
    g_ecol[pos] = c;
    g_ewn[pos] = w;
    g_erow[pos] = r;
}

// ---------------- conv1 + relu -> T0; zero B1 ----------------
__global__ __launch_bounds__(256) void k_conv(const float* __restrict__ xr,
                                              const float* __restrict__ xi,
                                              const float* __restrict__ wr,
                                              const float* __restrict__ wi,
                                              const float* __restrict__ br,
                                              const float* __restrict__ bi) {
    __shared__ float swr[100], swi[100], sbr[10], sbi[10];
    int t = threadIdx.x;
    if (t < 100) { swr[t] = wr[t]; swi[t] = wi[t]; }
    if (t < 10)  { sbr[t] = br[t]; sbi[t] = bi[t]; }
    __syncthreads();
    int n = blockIdx.x * 256 + t;
    float a[10], b_[10];
#pragma unroll
    for (int k = 0; k < 10; k++) { a[k] = xr[n * 10 + k]; b_[k] = xi[n * 10 + k]; }
    float* o = g_T0 + n * 20;
#pragma unroll
    for (int c = 0; c < 10; c++) {
        float yr = sbr[c], yi = sbi[c];
#pragma unroll
        for (int k = 0; k < 10; k++) {
            yr += a[k] * swr[c * 10 + k] - b_[k] * swi[c * 10 + k];
            yi += a[k] * swi[c * 10 + k] + b_[k] * swr[c * 10 + k];
        }
        o[c]      = fmaxf(yr, 0.f);
        o[10 + c] = fmaxf(yi, 0.f);
    }
    float4 z4 = make_float4(0.f, 0.f, 0.f, 0.f);
    float4* b1 = (float4*)(g_B1 + n * 20);
#pragma unroll
    for (int j = 0; j < 5; j++) b1[j] = z4;
}

// ---------------- CSR gather ----------------
__global__ __launch_bounds__(256) void k_gather(int phase) {
    const float* __restrict__ X = (phase == 0) ? g_T0 : g_B1;
    float* S = (phase == 0) ? g_B1 : g_B2;
    int t = blockIdx.x * 256 + threadIdx.x;
    int base = t * EC;

    int4 ci = *(const int4*)(g_ecol + base);
    int4 ri = *(const int4*)(g_erow + base);
    float4 wi4 = *(const float4*)(g_ewn + base);
    int c[EC] = {ci.x, ci.y, ci.z, ci.w};
    int r[EC] = {ri.x, ri.y, ri.z, ri.w};
    float w[EC] = {wi4.x, wi4.y, wi4.z, wi4.w};

    float4 v[EC][5];
#pragma unroll
    for (int j = 0; j < EC; j++) {
        const float4* src = (const float4*)(X + c[j] * 20);
#pragma unroll
        for (int k = 0; k < 5; k++) v[j][k] = src[k];
    }

    float acc[20];
    int cur = r[0];
#pragma unroll
    for (int k = 0; k < 5; k++) {
        acc[4 * k + 0] = w[0] * v[0][k].x;
        acc[4 * k + 1] = w[0] * v[0][k].y;
        acc[4 * k + 2] = w[0] * v[0][k].z;
        acc[4 * k + 3] = w[0] * v[0][k].w;
    }
#pragma unroll
    for (int j = 1; j < EC; j++) {
        if (r[j] != cur) {
            float* sp = S + cur * 20;
#pragma unroll
            for (int k = 0; k < 5; k++)
                red4(sp + 4 * k, acc[4 * k], acc[4 * k + 1], acc[4 * k + 2], acc[4 * k + 3]);
            cur = r[j];
#pragma unroll
            for (int k = 0; k < 20; k++) acc[k] = 0.f;
        }
#pragma unroll
        for (int k = 0; k < 5; k++) {
            acc[4 * k + 0] += w[j] * v[j][k].x;
            acc[4 * k + 1] += w[j] * v[j][k].y;
            acc[4 * k + 2] += w[j] * v[j][k].z;
            acc[4 * k + 3] += w[j] * v[j][k].w;
        }
    }
    float* sp = S + cur * 20;
#pragma unroll
    for (int k = 0; k < 5; k++)
        red4(sp + 4 * k, acc[4 * k], acc[4 * k + 1], acc[4 * k + 2], acc[4 * k + 3]);
}

// ---------------- pointwise: T1 = T0 - S1; zero B2 ----------------
__global__ void k_t1() {
    int i = blockIdx.x * 256 + threadIdx.x;
    float4 t0 = ((const float4*)g_T0)[i];
    float4 s  = ((const float4*)g_B1)[i];
    ((float4*)g_B1)[i] = make_float4(t0.x - s.x, t0.y - s.y, t0.z - s.z, t0.w - s.w);
    ((float4*)g_B2)[i] = make_float4(0.f, 0.f, 0.f, 0.f);
}

// ---------------- cheb combine ----------------
__global__ __launch_bounds__(256) void k_cheb(const float* __restrict__ cw,
                                              const float* __restrict__ cb) {
    __shared__ float scw[300], scb[10];
    int t = threadIdx.x;
    for (int i = t; i < 300; i += 256) scw[i] = cw[i];
    if (t < 10) scb[t] = cb[t];
    __syncthreads();
    int n = blockIdx.x * 256 + t;
    float t0[20], t1[20], t2[20];
#pragma unroll
    for (int j = 0; j < 20; j++) {
        t0[j] = g_T0[n * 20 + j];
        t1[j] = g_B1[n * 20 + j];
        t2[j] = 2.f * (t1[j] - g_B2[n * 20 + j]) - t0[j];
    }
    int b = n >> 11;
    int nl = n & (NPG - 1);
    int base = b * KDIM + nl * 10;
#pragma unroll
    for (int o = 0; o < 10; o++) {
        float ar = scb[o], ai = 0.f;
#pragma unroll
        for (int i2 = 0; i2 < 10; i2++) {
            float w0 = scw[i2 * 10 + o], w1 = scw[100 + i2 * 10 + o], w2 = scw[200 + i2 * 10 + o];
            ar += t0[i2] * w0 + t1[i2] * w1 + t2[i2] * w2;
            ai += t0[10 + i2] * w0 + t1[10 + i2] * w1 + t2[10 + i2] * w2;
        }
        g_zr[base + o] = fmaxf(ar, 0.f);
        g_zi[base + o] = fmaxf(ai, 0.f);
    }
}

// ---------------- zero GEMM accumulators ----------------
__global__ void k_zacc() {
    int i = blockIdx.x * 256 + threadIdx.x;
    g_accU[i] = 0.f;
}

// ---------------- fc1 complex GEMM via mma.sync bf16 split-precision ----------------
// Grid (4 M-tiles of 128 W-rows, 32 k-splits of 640). 256 threads (8 warps x 16 rows).
__global__ __launch_bounds__(256, 1) void k_fc1_mma(const float* __restrict__ Wr,
                                                    const float* __restrict__ Wi) {
    extern __shared__ __align__(16) __nv_bfloat16 sm[];
    const int t = threadIdx.x;
    const int wid = t >> 5, lane = t & 31;
    const int q = lane & 3, rl = lane >> 2;
    const int h0 = blockIdx.x * 128;
    const int kb0 = blockIdx.y * FC1_KBLK;

    // conversion-phase indices
    const int rowA = t >> 1;              // 0..127
    const int segA = (t & 1) * 16;        // 0 or 16
    const int rowZ = (t & 127) >> 1;      // 0..63
    const int segZ = ((t & 127) & 1) * 16;
    const bool doZi = (t >= 128);

    float ur[8][4], ui[8][4];
#pragma unroll
    for (int n = 0; n < 8; n++)
#pragma unroll
        for (int j = 0; j < 4; j++) { ur[n][j] = 0.f; ui[n][j] = 0.f; }

    for (int c = 0; c < FC1_NCH; c++) {
        const int kb = kb0 + c * FC1_KCH;
        // global loads (issued before sync to overlap previous chunk's MMAs)
        float fwr[16], fwi[16], fz[16];
        {
            const float4* p = (const float4*)(Wr + rowA * KDIM + h0 * KDIM + kb + segA);
#pragma unroll
            for (int j = 0; j < 4; j++) {
                float4 v = p[j];
                fwr[4 * j] = v.x; fwr[4 * j + 1] = v.y; fwr[4 * j + 2] = v.z; fwr[4 * j + 3] = v.w;
            }
            p = (const float4*)(Wi + rowA * KDIM + h0 * KDIM + kb + segA);
#pragma unroll
            for (int j = 0; j < 4; j++) {
                float4 v = p[j];
                fwi[4 * j] = v.x; fwi[4 * j + 1] = v.y; fwi[4 * j + 2] = v.z; fwi[4 * j + 3] = v.w;
            }
            const float* zsrc = doZi ? g_zi : g_zr;
            p = (const float4*)(zsrc + rowZ * KDIM + kb + segZ);
#pragma unroll
            for (int j = 0; j < 4; j++) {
                float4 v = p[j];
                fz[4 * j] = v.x; fz[4 * j + 1] = v.y; fz[4 * j + 2] = v.z; fz[4 * j + 3] = v.w;
            }
        }
        __syncthreads();   // previous chunk's compute done
        // convert + store to padded smem
        {
            uint32_t hi, lo;
            int basew = rowA * SA + segA;
#pragma unroll
            for (int j = 0; j < 8; j++) {
                cvt_pair(fwr[2 * j], fwr[2 * j + 1], hi, lo);
                *(uint32_t*)&sm[OFF_WRH + basew + 2 * j] = hi;
                *(uint32_t*)&sm[OFF_WRL + basew + 2 * j] = lo;
            }
#pragma unroll
            for (int j = 0; j < 8; j++) {
                cvt_pair(fwi[2 * j], fwi[2 * j + 1], hi, lo);
                *(uint32_t*)&sm[OFF_WIH + basew + 2 * j] = hi;
                *(uint32_t*)&sm[OFF_WIL + basew + 2 * j] = lo;
            }
            int basez = rowZ * SA + segZ;
            int oh = doZi ? OFF_ZIH : OFF_ZRH;
            int ol = doZi ? OFF_ZIL : OFF_ZRL;
#pragma unroll
            for (int j = 0; j < 8; j++) {
                cvt_pair(fz[2 * j], fz[2 * j + 1], hi, lo);
                *(uint32_t*)&sm[oh + basez + 2 * j] = hi;
                *(uint32_t*)&sm[ol + basez + 2 * j] = lo;
            }
        }
        __syncthreads();
        // compute: 2 k16 steps
        const int r0 = wid * 16;
#pragma unroll
        for (int kk = 0; kk < FC1_KCH; kk += 16) {
            uint32_t awrh[4], awrl[4], awih[4], awil[4], nwih[4], nwil[4];
            int a00 = (r0 + rl) * SA + kk + 2 * q;
            int a10 = (r0 + rl + 8) * SA + kk + 2 * q;
            awrh[0] = *(const uint32_t*)&sm[OFF_WRH + a00];
            awrh[1] = *(const uint32_t*)&sm[OFF_WRH + a10];
            awrh[2] = *(const uint32_t*)&sm[OFF_WRH + a00 + 8];
            awrh[3] = *(const uint32_t*)&sm[OFF_WRH + a10 + 8];
            awrl[0] = *(const uint32_t*)&sm[OFF_WRL + a00];
            awrl[1] = *(const uint32_t*)&sm[OFF_WRL + a10];
            awrl[2] = *(const uint32_t*)&sm[OFF_WRL + a00 + 8];
            awrl[3] = *(const uint32_t*)&sm[OFF_WRL + a10 + 8];
            awih[0] = *(const uint32_t*)&sm[OFF_WIH + a00];
            awih[1] = *(const uint32_t*)&sm[OFF_WIH + a10];
            awih[2] = *(const uint32_t*)&sm[OFF_WIH + a00 + 8];
            awih[3] = *(const uint32_t*)&sm[OFF_WIH + a10 + 8];
            awil[0] = *(const uint32_t*)&sm[OFF_WIL + a00];
            awil[1] = *(const uint32_t*)&sm[OFF_WIL + a10];
            awil[2] = *(const uint32_t*)&sm[OFF_WIL + a00 + 8];
            awil[3] = *(const uint32_t*)&sm[OFF_WIL + a10 + 8];
#pragma unroll
            for (int j = 0; j < 4; j++) {
                nwih[j] = awih[j] ^ 0x80008000u;
                nwil[j] = awil[j] ^ 0x80008000u;
            }
#pragma unroll
            for (int nt = 0; nt < 8; nt++) {
                uint32_t bzrh[2], bzrl[2], bzih[2], bzil[2];
                int b0 = (nt * 8 + rl) * SA + kk + 2 * q;
                bzrh[0] = *(const uint32_t*)&sm[OFF_ZRH + b0];
                bzrh[1] = *(const uint32_t*)&sm[OFF_ZRH + b0 + 8];
                bzrl[0] = *(const uint32_t*)&sm[OFF_ZRL + b0];
                bzrl[1] = *(const uint32_t*)&sm[OFF_ZRL + b0 + 8];
                bzih[0] = *(const uint32_t*)&sm[OFF_ZIH + b0];
                bzih[1] = *(const uint32_t*)&sm[OFF_ZIH + b0 + 8];
                bzil[0] = *(const uint32_t*)&sm[OFF_ZIL + b0];
                bzil[1] = *(const uint32_t*)&sm[OFF_ZIL + b0 + 8];
                // ur = Wr*zr - Wi*zi  (hi*hi + hi*lo + lo*hi)
                mma16816(ur[nt], awrh, bzrh);
                mma16816(ur[nt], awrh, bzrl);
                mma16816(ur[nt], awrl, bzrh);
                mma16816(ur[nt], nwih, bzih);
                mma16816(ur[nt], nwih, bzil);
                mma16816(ur[nt], nwil, bzih);
                // ui = Wi*zr + Wr*zi
                mma16816(ui[nt], awih, bzrh);
                mma16816(ui[nt], awih, bzrl);
                mma16816(ui[nt], awil, bzrh);
                mma16816(ui[nt], awrh, bzih);
                mma16816(ui[nt], awrh, bzil);
                mma16816(ui[nt], awrl, bzih);
            }
        }
    }
    // epilogue: atomic accumulate into g_accU
    const int hbase = h0 + wid * 16 + rl;
#pragma unroll
    for (int nt = 0; nt < 8; nt++) {
        int n = nt * 8 + 2 * q;
        atomicAdd(&g_accU[n * HID + hbase],           ur[nt][0]);
        atomicAdd(&g_accU[(n + 1) * HID + hbase],     ur[nt][1]);
        atomicAdd(&g_accU[n * HID + hbase + 8],       ur[nt][2]);
        atomicAdd(&g_accU[(n + 1) * HID + hbase + 8], ur[nt][3]);
        atomicAdd(&g_accU[BATCH * HID + n * HID + hbase],           ui[nt][0]);
        atomicAdd(&g_accU[BATCH * HID + (n + 1) * HID + hbase],     ui[nt][1]);
        atomicAdd(&g_accU[BATCH * HID + n * HID + hbase + 8],       ui[nt][2]);
        atomicAdd(&g_accU[BATCH * HID + (n + 1) * HID + hbase + 8], ui[nt][3]);
    }
}

// ---------------- bias + relu -> cat ----------------
__global__ void k_relu_cat(const float* __restrict__ fbr, const float* __restrict__ fbi) {
    int i = blockIdx.x * 256 + threadIdx.x;
    int b = i >> 9, h = i & 511;
    g_cat[b * 1024 + h]       = fmaxf(g_accU[i] + fbr[h], 0.f);
    g_cat[b * 1024 + 512 + h] = fmaxf(g_accU[BATCH * HID + i] + fbi[h], 0.f);
}

// ---------------- heads ----------------
__global__ __launch_bounds__(128) void k_head(const float* __restrict__ aw,
                                              const float* __restrict__ ab,
                                              const float* __restrict__ cw,
                                              const float* __restrict__ cb,
                                              float* __restrict__ out) {
    __shared__ float s[1024];
    int b = blockIdx.x;
    for (int i = threadIdx.x; i < 1024; i += 128) s[i] = g_cat[b * 1024 + i];
    __syncthreads();
    int warp = threadIdx.x >> 5, lane = threadIdx.x & 31;
    for (int o = warp; o < 33; o += 4) {
        const float* wrow = (o < 32) ? (aw + o * 1024) : cw;
        float acc = 0.f;
        for (int k = lane; k < 1024; k += 32) acc += s[k] * wrow[k];
#pragma unroll
        for (int off = 16; off; off >>= 1) acc += __shfl_down_sync(0xffffffffu, acc, off);
        if (lane == 0) {
            if (o < 32) out[b * 32 + o] = acc + ab[o];
            else        out[BATCH * 32 + b] = acc + cb[0];
        }
    }
}

// ---------------- launch ----------------
extern "C" void kernel_launch(void* const* d_in, const int* in_sizes, int n_in,
                              void* d_out, int out_size) {
    const float* xr   = (const float*)d_in[0];
    const float* xi   = (const float*)d_in[1];
    const float* ew   = (const float*)d_in[2];
    const float* c1wr = (const float*)d_in[3];
    const float* c1wi = (const float*)d_in[4];
    const float* c1br = (const float*)d_in[5];
    const float* c1bi = (const float*)d_in[6];
    const float* chw  = (const float*)d_in[7];
    const float* chb  = (const float*)d_in[8];
    const float* f1wr = (const float*)d_in[9];
    const float* f1wi = (const float*)d_in[10];
    const float* f1br = (const float*)d_in[11];
    const float* f1bi = (const float*)d_in[12];
    const float* cw   = (const float*)d_in[13];
    const float* cb   = (const float*)d_in[14];
    const float* aw   = (const float*)d_in[15];
    const float* ab   = (const float*)d_in[16];
    const int*   ei   = (const int*)d_in[17];
    const int* row = ei;
    const int* col = ei + NEDGE;
    float* out = (float*)d_out;

    cudaFuncSetAttribute(k_fc1_mma, cudaFuncAttributeMaxDynamicSharedMemorySize, FC1_SMEM_BYTES);

    k_init<<<NNODE / 256, 256>>>();
    k_degcnt<<<NEDGE / 256, 256>>>(row, ew);
    k_scan1<<<NNODE / 256, 256>>>();
    k_scan2<<<1, 512>>>();
    k_scan3<<<NNODE / 256, 256>>>();
    k_fill<<<NEDGE / 256, 256>>>(row, col, ew);
    k_conv<<<NNODE / 256, 256>>>(xr, xi, c1wr, c1wi, c1br, c1bi);
    k_gather<<<NEDGE / EC / 256, 256>>>(0);
    k_t1<<<(NNODE * 5) / 256, 256>>>();
    k_gather<<<NEDGE / EC / 256, 256>>>(1);
    k_cheb<<<NNODE / 256, 256>>>(chw, chb);
    k_zacc<<<(2 * BATCH * HID) / 256, 256>>>();
    k_fc1_mma<<<dim3(4, FC1_KS), 256, FC1_SMEM_BYTES>>>(f1wr, f1wi);
    k_relu_cat<<<(BATCH * HID) / 256, 256>>>(f1br, f1bi);
    k_head<<<BATCH, 128>>>(aw, ab, cw, cb, out);
}